// round 9
// baseline (speedup 1.0000x reference)
#include <cuda_runtime.h>
#include <cuda_bf16.h>
#include <cstddef>

// Soft-Viterbi (NW-style) DP, N=M=2048, 3 states (m,x,y), computed entirely
// in LINEAR space with per-lane power-of-2 scaling:
//   state E = exp(V - K*ln2), K integer. lse3 -> FFMA dot products.
//   em(i,j) = e^theta_m * (dm*e^a00 + dx*e^a01 + dy*e^a02)   (diag = V[i-1,j-1])
//   ex(i,j) = e^theta_x * (pm*e^a10 + px*e^a11 + py*e^a12)   (up   = V[i-1,j])
//   ey(i,j) = e^theta_y * (lm*e^a20 + lx*e^a21 + ly*e^a22)   (left = V[i,j-1])
// Boundary V=-1e8 -> exactly 0 in linear space. Output: K*ln2 + log(em+ex+ey).
//
// Barrier-free warp-shuffle systolic array:
//   64 CTAs x 32 lanes, one column per lane, lane l skewed l rows behind
//   lane l-1. Edges cross lanes via __shfl_up_sync into a 2-deep history
//   (left = row i, diag = row i-1) -- no SMEM, no __syncthreads.
//   CTA boundaries: producer lane 31 streams its column to a global edge
//   buffer, publishing a progress counter (st.release) every 4 rows;
//   consumer lane 0 keeps a 4-deep register prefetch queue so the L2
//   round-trip hides under 4 steps.

#define NN 2048
#define MM 2048
#define G  64
#define T  32
#define STEPS (NN + T - 1)

static_assert(G * T == MM, "column coverage");

// g_edge[b][i] = linear-space V[i, (b+1)*T] as (em, ex, ey, K-as-float-bits)
__device__ float4 g_edge[G - 1][NN + 1];
__device__ int    g_prog[G - 1];

__device__ __forceinline__ int ld_acq(const int* p) {
    int v;
    asm volatile("ld.global.acquire.gpu.b32 %0, [%1];" : "=r"(v) : "l"(p) : "memory");
    return v;
}
__device__ __forceinline__ void st_rel(int* p, int v) {
    asm volatile("st.global.release.gpu.b32 [%0], %1;" :: "l"(p), "r"(v) : "memory");
}
// 2^n as float, clamped to normal range (n <= 0 uses underflow-to-tiny, fine)
__device__ __forceinline__ float exp2i(int n) {
    n = max(-126, min(127, n));
    return __int_as_float((n + 127) << 23);
}

__global__ void viterbi_init_kernel() {
    if (threadIdx.x < G - 1) g_prog[threadIdx.x] = 0;
}

__global__ __launch_bounds__(T, 1)
void ViterbiDecoder_5506148073875_kernel(const float* __restrict__ theta,
                                         const float* __restrict__ A,
                                         float* __restrict__ out) {
    const int g = blockIdx.x;
    const int l = threadIdx.x;
    const int j = g * T + l;  // 0-based column (theta column index)

    // exp of transition matrix (9 scalars, once)
    const float ea00 = __expf(A[0]), ea01 = __expf(A[1]), ea02 = __expf(A[2]);
    const float ea10 = __expf(A[3]), ea11 = __expf(A[4]), ea12 = __expf(A[5]);
    const float ea20 = __expf(A[6]), ea21 = __expf(A[7]), ea22 = __expf(A[8]);

    // Own previous-row state (linear, scale K). Row 0 (V=-inf) -> zeros.
    float pm = 0.f, px = 0.f, py = 0.f;
    int   K  = 0;

    // Neighbor history: h1 = row i (left), h2 = row i-1 (diag) of column j-1.
    float h1m = 0.f, h1x = 0.f, h1y = 0.f; int h1k = 0;
    float h2m = 0.f, h2x = 0.f, h2y = 0.f; int h2k = 0;

    // Lane-0 (g>0) edge prefetch queue: q1=row i+1, q2=row i+2, q3=row i+3.
    float4 q1 = {0,0,0,0}, q2 = {0,0,0,0}, q3 = {0,0,0,0};
    int known = 0;
    const int* pp = (g > 0) ? &g_prog[g - 1] : nullptr;

    if (l == 0) {
        if (g == 0) {
            h2m = 1.f;  // diag for row 1 = V[0,0] = [0,-inf,-inf] -> (1,0,0), K=0
        } else {
            while ((known = ld_acq(pp)) < 4) { }
            float4 e1 = g_edge[g - 1][1];
            h1m = e1.x; h1x = e1.y; h1y = e1.z; h1k = __float_as_int(e1.w);
            q1 = g_edge[g - 1][2];
            q2 = g_edge[g - 1][3];
            q3 = g_edge[g - 1][4];
        }
    }

    // Theta for this lane's first row (row 1).
    float th0, th1, th2;
    {
        const float* tp = theta + (size_t)j * 3;
        th0 = tp[0]; th1 = tp[1]; th2 = tp[2];
    }

    for (int s = 0; s < STEPS; ++s) {
        const int  i   = s - l + 1;          // 1-based row this lane computes
        const bool act = (i >= 1 && i <= NN);

        if (act) {
            // Align all operands to the largest scale (factors <= 1: safe).
            const int kref = max(K, max(h1k, h2k));
            const float fo = exp2i(K   - kref);
            const float fl = exp2i(h1k - kref);
            const float fd = exp2i(h2k - kref);

            const float tm = __expf(th0), tx = __expf(th1), ty = __expf(th2);

            const float nm = tm * (fmaf(h2m * fd, ea00,
                                   fmaf(h2x * fd, ea01, (h2y * fd) * ea02)));
            const float nx = tx * (fmaf(pm * fo, ea10,
                                   fmaf(px * fo, ea11, (py * fo) * ea12)));
            const float ny = ty * (fmaf(h1m * fl, ea20,
                                   fmaf(h1x * fl, ea21, (h1y * fl) * ea22)));

            // Renormalize so max state lands in [1,2).
            const float mx = fmaxf(fmaxf(nm, nx), ny);   // > 0 for all DP cells
            const int   sh = ((__float_as_int(mx) >> 23) & 0xff) - 127;
            const float fn = exp2i(-sh);
            pm = nm * fn; px = nx * fn; py = ny * fn;
            K  = kref + sh;

            // Cross-CTA publish (producer = last lane).
            if (l == T - 1 && g < G - 1) {
                g_edge[g][i] = make_float4(pm, px, py, __int_as_float(K));
                if ((i & 3) == 0 || i == NN) st_rel(&g_prog[g], i);
            }

            if (g == G - 1 && l == T - 1 && i == NN)
                out[0] = (float)K * 0.69314718055994531f + __logf(pm + px + py);
        }

        // Pass edge to lane l+1 (warp-synchronous; no barrier).
        const float rm = __shfl_up_sync(0xffffffffu, pm, 1);
        const float rx = __shfl_up_sync(0xffffffffu, px, 1);
        const float ry = __shfl_up_sync(0xffffffffu, py, 1);
        const int   rk = __shfl_up_sync(0xffffffffu, K, 1);

        // Rotate neighbor history.
        h2m = h1m; h2x = h1x; h2y = h1y; h2k = h1k;
        if (l == 0) {
            if (g > 0) {
                h1m = q1.x; h1x = q1.y; h1y = q1.z; h1k = __float_as_int(q1.w);
                q1 = q2; q2 = q3;
                const int need = i + 4;  // row to prefetch (used 4 steps later)
                if (need <= NN) {
                    if (known < need)
                        while ((known = ld_acq(pp)) < need) { }
                    q3 = g_edge[g - 1][need];
                } else {
                    q3 = make_float4(0.f, 0.f, 0.f, 0.f);
                }
            } else {
                h1m = 0.f; h1x = 0.f; h1y = 0.f; h1k = 0;  // V[i,0] = -inf
            }
        } else {
            h1m = rm; h1x = rx; h1y = ry; h1k = rk;
        }

        // Prefetch theta for next row.
        const int inext = i + 1;
        if (inext >= 1 && inext <= NN) {
            const float* tp = theta + ((size_t)(inext - 1) * MM + j) * 3;
            th0 = tp[0]; th1 = tp[1]; th2 = tp[2];
        }
    }
}

extern "C" void kernel_launch(void* const* d_in, const int* in_sizes, int n_in,
                              void* d_out, int out_size) {
    const float* theta = (const float*)d_in[0];
    const float* A     = (const float*)d_in[1];
    if (n_in >= 2 && in_sizes[0] == 9) {  // defensive: swap if metadata order differs
        theta = (const float*)d_in[1];
        A     = (const float*)d_in[0];
    }
    viterbi_init_kernel<<<1, G>>>();  // reset cross-CTA progress (per replay)
    ViterbiDecoder_5506148073875_kernel<<<G, T>>>(theta, A, (float*)d_out);
}

// round 10
// speedup vs baseline: 1.6251x; 1.6251x over previous
#include <cuda_runtime.h>
#include <cuda_bf16.h>
#include <cstddef>

// Soft-Viterbi DP (N=M=2048, 3 states) in LINEAR space with per-lane
// power-of-2 scaling: state E = exp(V - K*ln2). lse3 -> FFMA dot products.
// Boundary V=-1e8 -> exactly 0 (validated: rel_err 3.3e-6 in R9).
//
// Structure: G=16 CTAs x 32 lanes x C=4 columns/lane, barrier-free
// warp-shuffle systolic array. Lane l computes row i = s-l+1 (4 cells) at
// step s. Neighbor edge via __shfl_up into a 2-deep history (left=row i,
// diag=row i-1). Deep register pipelines hide memory latency:
//   - theta: 3-row lookahead queue (3 aligned float4 per row).
//   - cross-CTA edge: 4-row float4 queue + cached progress counter
//     (st.release by producer every 2 rows; consumer polls only on need).

#define NN 2048
#define MM 2048
#define G  16
#define T  32
#define C  4
#define W  (T * C)            // 128 columns per CTA
#define STEPS (NN + T - 1)

static_assert(G * W == MM, "column coverage");

__device__ float4 g_edge[G - 1][NN + 1];  // (em,ex,ey,K-bits) of col (g+1)*W
__device__ int    g_prog[G - 1];

__device__ __forceinline__ int ld_acq(const int* p) {
    int v;
    asm volatile("ld.global.acquire.gpu.b32 %0, [%1];" : "=r"(v) : "l"(p) : "memory");
    return v;
}
__device__ __forceinline__ void st_rel(int* p, int v) {
    asm volatile("st.global.release.gpu.b32 [%0], %1;" :: "l"(p), "r"(v) : "memory");
}
__device__ __forceinline__ float exp2i(int n) {  // 2^n, clamped to normals
    n = max(-126, min(127, n));
    return __int_as_float((n + 127) << 23);
}

__global__ void viterbi_init_kernel() {
    if (threadIdx.x < G - 1) g_prog[threadIdx.x] = 0;
}

__global__ __launch_bounds__(T, 1)
void ViterbiDecoder_5506148073875_kernel(const float* __restrict__ theta,
                                         const float* __restrict__ A,
                                         float* __restrict__ out) {
    const int g  = blockIdx.x;
    const int l  = threadIdx.x;
    const int jb = g * W + l * C;  // 0-based first theta column of this lane

    const float ea00 = __expf(A[0]), ea01 = __expf(A[1]), ea02 = __expf(A[2]);
    const float ea10 = __expf(A[3]), ea11 = __expf(A[4]), ea12 = __expf(A[5]);
    const float ea20 = __expf(A[6]), ea21 = __expf(A[7]), ea22 = __expf(A[8]);

    // Previous-row state for 4 cells: p[c*3 + {m,x,y}], common scale K.
    float p[12];
#pragma unroll
    for (int k = 0; k < 12; ++k) p[k] = 0.f;   // row 0: V=-inf -> 0
    int K = 0;

    // Neighbor (col jb, 1-based) history: h1 = row i (left), h2 = row i-1 (diag).
    float h1m = 0.f, h1x = 0.f, h1y = 0.f; int h1k = 0;
    float h2m = 0.f, h2x = 0.f, h2y = 0.f; int h2k = 0;
    if (g == 0 && l == 0) h2m = 1.f;  // V[0,0] = [0,-inf,-inf] -> (1,0,0)

    // ---- theta pipeline: th_e = exp(theta row i); u = row i+1; v = row i+2.
    const float4* tbase = reinterpret_cast<const float4*>(theta);
    auto trow = [&](int r) {  // r is 1-based row; returns float4* to 12 floats
        return tbase + ((size_t)(r - 1) * MM + jb) * 3 / 4;
    };
    float th_e[12];
    float4 u0, u1, u2, v0, v1, v2;
    {
        const float4* r1 = trow(1); float4 w0 = r1[0], w1 = r1[1], w2 = r1[2];
        const float4* r2 = trow(2); u0 = r2[0]; u1 = r2[1]; u2 = r2[2];
        const float4* r3 = trow(3); v0 = r3[0]; v1 = r3[1]; v2 = r3[2];
        th_e[0] = __expf(w0.x); th_e[1] = __expf(w0.y); th_e[2]  = __expf(w0.z);
        th_e[3] = __expf(w0.w); th_e[4] = __expf(w1.x); th_e[5]  = __expf(w1.y);
        th_e[6] = __expf(w1.z); th_e[7] = __expf(w1.w); th_e[8]  = __expf(w2.x);
        th_e[9] = __expf(w2.y); th_e[10] = __expf(w2.z); th_e[11] = __expf(w2.w);
    }

    // ---- cross-CTA edge pipeline (consumer: lane 0 of g > 0).
    const int* pp = (g > 0) ? &g_prog[g - 1] : nullptr;
    int known = 0;
    float4 q0 = {0,0,0,0}, q1 = {0,0,0,0}, q2 = {0,0,0,0}, q3 = {0,0,0,0};
    if (g > 0 && l == 0) {
        while ((known = ld_acq(pp)) < 5) { }
        float4 e = g_edge[g - 1][1];
        h1m = e.x; h1x = e.y; h1y = e.z; h1k = __float_as_int(e.w);
        q0 = g_edge[g - 1][2]; q1 = g_edge[g - 1][3];
        q2 = g_edge[g - 1][4]; q3 = g_edge[g - 1][5];
    }

    for (int s = 0; s < STEPS; ++s) {
        const int i = s - l + 1;  // 1-based row this lane computes

        // Issue theta load for row i+3 (consumed ~2.2 steps later).
        float4 t0, t1, t2;
        const int rth = i + 3;
        const bool ldth = (rth >= 4 && rth <= NN);
        if (ldth) { const float4* tp = trow(rth); t0 = tp[0]; t1 = tp[1]; t2 = tp[2]; }

        if (i >= 1 && i <= NN) {
            // Align all operands to the largest scale.
            const int kref = max(K, max(h1k, h2k));
            const float fo = exp2i(K   - kref);
            const float fl = exp2i(h1k - kref);
            const float fd = exp2i(h2k - kref);

            float sp[12];
#pragma unroll
            for (int k = 0; k < 12; ++k) sp[k] = p[k] * fo;

            float dm = h2m * fd, dx = h2x * fd, dy = h2y * fd;  // diag, cell 0
            float lm = h1m * fl, lx = h1x * fl, ly = h1y * fl;  // left, cell 0

            float n[12];
#pragma unroll
            for (int c = 0; c < 4; ++c) {
                const float cdm = (c == 0) ? dm : sp[3*c - 3];
                const float cdx = (c == 0) ? dx : sp[3*c - 2];
                const float cdy = (c == 0) ? dy : sp[3*c - 1];
                const float clm = (c == 0) ? lm : n[3*c - 3];
                const float clx = (c == 0) ? lx : n[3*c - 2];
                const float cly = (c == 0) ? ly : n[3*c - 1];
                n[3*c + 0] = th_e[3*c + 0] *
                    fmaf(cdm, ea00, fmaf(cdx, ea01, cdy * ea02));
                n[3*c + 1] = th_e[3*c + 1] *
                    fmaf(sp[3*c], ea10, fmaf(sp[3*c+1], ea11, sp[3*c+2] * ea12));
                n[3*c + 2] = th_e[3*c + 2] *
                    fmaf(clm, ea20, fmaf(clx, ea21, cly * ea22));
            }

            // Renormalize row to keep max in [1,2); bump scale K.
            float mx = n[0];
#pragma unroll
            for (int k = 1; k < 12; ++k) mx = fmaxf(mx, n[k]);
            const int   sh = ((__float_as_int(mx) >> 23) & 0xff) - 127;
            const float fn = exp2i(-sh);
#pragma unroll
            for (int k = 0; k < 12; ++k) p[k] = n[k] * fn;
            K = kref + sh;

            if (l == T - 1 && g < G - 1) {  // producer: publish last cell
                g_edge[g][i] = make_float4(p[9], p[10], p[11], __int_as_float(K));
                if ((i & 1) == 0 || i == NN) st_rel(&g_prog[g], i);
            }
            if (g == G - 1 && l == T - 1 && i == NN)
                out[0] = (float)K * 0.69314718055994531f +
                         __logf(p[9] + p[10] + p[11]);
        }

        // Pass edge (last cell, renormed) to lane l+1; rotate history.
        const float rm = __shfl_up_sync(0xffffffffu, p[9],  1);
        const float rx = __shfl_up_sync(0xffffffffu, p[10], 1);
        const float ry = __shfl_up_sync(0xffffffffu, p[11], 1);
        const int   rk = __shfl_up_sync(0xffffffffu, K, 1);

        h2m = h1m; h2x = h1x; h2y = h1y; h2k = h1k;
        if (l == 0) {
            if (g > 0) {
                h1m = q0.x; h1x = q0.y; h1y = q0.z; h1k = __float_as_int(q0.w);
                q0 = q1; q1 = q2; q2 = q3;
                const int f = i + 5;  // refill queue tail
                if (f <= NN) {
                    if (known < f) { while ((known = ld_acq(pp)) < f) { } }
                    q3 = g_edge[g - 1][f];
                } else {
                    q3 = make_float4(0.f, 0.f, 0.f, 0.f);
                }
            } else {
                h1m = 0.f; h1x = 0.f; h1y = 0.f; h1k = 0;  // V[i,0] = -inf
            }
        } else {
            h1m = rm; h1x = rx; h1y = ry; h1k = rk;
        }

        // Rotate theta pipeline for next row (row 1 came from prologue).
        const int inext = i + 1;
        if (inext >= 2 && inext <= NN) {
            th_e[0] = __expf(u0.x); th_e[1] = __expf(u0.y); th_e[2]  = __expf(u0.z);
            th_e[3] = __expf(u0.w); th_e[4] = __expf(u1.x); th_e[5]  = __expf(u1.y);
            th_e[6] = __expf(u1.z); th_e[7] = __expf(u1.w); th_e[8]  = __expf(u2.x);
            th_e[9] = __expf(u2.y); th_e[10] = __expf(u2.z); th_e[11] = __expf(u2.w);
            u0 = v0; u1 = v1; u2 = v2;
            v0 = t0; v1 = t1; v2 = t2;
        }
    }
}

extern "C" void kernel_launch(void* const* d_in, const int* in_sizes, int n_in,
                              void* d_out, int out_size) {
    const float* theta = (const float*)d_in[0];
    const float* A     = (const float*)d_in[1];
    if (n_in >= 2 && in_sizes[0] == 9) {  // defensive: swap if order differs
        theta = (const float*)d_in[1];
        A     = (const float*)d_in[0];
    }
    viterbi_init_kernel<<<1, G>>>();  // reset cross-CTA progress (per replay)
    ViterbiDecoder_5506148073875_kernel<<<G, T>>>(theta, A, (float*)d_out);
}